// round 1
// baseline (speedup 1.0000x reference)
#include <cuda_runtime.h>
#include <cuda_bf16.h>
#include <cstdint>

// Problem constants
#define NN 50000
#define EE 800000
#define LDBIG 1312   // 4*256 (W) + 256 (skip) + 16 (ES) + 16 (ED)
#define LD2   24     // 8 (W) + 2 (skip) + 4 (ES) + 4 (ED) + 6 pad

// ---------------- static device scratch (no allocation allowed) ----------------
__device__ float g_XA[(size_t)NN * 256];           // normalized x
__device__ float g_XB[(size_t)NN * 256];           // layer output x
__device__ float g_HB[(size_t)NN * LDBIG];         // hidden buffer (h0..h3 | skip | ES | ED)
__device__ float g_Wp[256 * LDBIG];                // packed weights
__device__ float g_sum[256], g_sumsq[256], g_mean[256], g_rstd[256];
__device__ int   g_deg[NN], g_off[NN + 1], g_cnt[NN];
__device__ int   g_ssrc[EE];
__device__ unsigned char g_scls[EE];

// ---------------- CSR build ----------------
__global__ void hist_kernel(const int* __restrict__ eidx, int* __restrict__ deg, int E, int n) {
    int e = blockIdx.x * blockDim.x + threadIdx.x;
    if (e >= E) return;
    int d = eidx[E + e];
    if ((unsigned)d < (unsigned)n) atomicAdd(&deg[d], 1);
}

__global__ void scan_kernel(const int* __restrict__ deg, int* __restrict__ off, int n) {
    __shared__ int sm[1024];
    __shared__ int carry_s;
    int t = threadIdx.x;
    if (t == 0) { off[0] = 0; carry_s = 0; }
    __syncthreads();
    for (int base = 0; base < n; base += 1024) {
        int v = (base + t < n) ? deg[base + t] : 0;
        sm[t] = v;
        __syncthreads();
        for (int d = 1; d < 1024; d <<= 1) {
            int add = (t >= d) ? sm[t - d] : 0;
            __syncthreads();
            sm[t] += add;
            __syncthreads();
        }
        if (base + t < n) off[base + t + 1] = sm[t] + carry_s;
        __syncthreads();
        if (t == 1023) carry_s += sm[1023];
        __syncthreads();
    }
}

__global__ void fill_kernel(const int* __restrict__ eidx, const int* __restrict__ eattr,
                            const int* __restrict__ off, int* __restrict__ cnt,
                            int* __restrict__ ssrc, unsigned char* __restrict__ scls,
                            int E, int n) {
    int e = blockIdx.x * blockDim.x + threadIdx.x;
    if (e >= E) return;
    int s = eidx[e];
    int d = eidx[E + e];
    int c = eattr[e];
    if ((unsigned)d >= (unsigned)n) return;
    int pos = off[d] + atomicAdd(&cnt[d], 1);
    ssrc[pos] = s;
    scls[pos] = (unsigned char)((c >= 0 && c < 4) ? c : 255);
}

// ---------------- batchnorm ----------------
__global__ void colstats_kernel(const float* __restrict__ x, float* __restrict__ sum,
                                float* __restrict__ sumsq, int n, int din) {
    int t = threadIdx.x;
    int c = t % din;
    int rpb = blockDim.x / din;
    int r0 = blockIdx.x * rpb + t / din;
    int rstride = gridDim.x * rpb;
    float s = 0.f, q = 0.f;
    for (int r = r0; r < n; r += rstride) {
        float v = x[(size_t)r * din + c];
        s += v; q += v * v;
    }
    atomicAdd(&sum[c], s);
    atomicAdd(&sumsq[c], q);
}

__global__ void finalize_kernel(const float* __restrict__ sum, const float* __restrict__ sumsq,
                                float* __restrict__ mean, float* __restrict__ rstd, int n, int din) {
    int c = threadIdx.x;
    if (c >= din) return;
    float m = sum[c] / (float)n;
    float v = sumsq[c] / (float)n - m * m;
    v = v > 0.f ? v : 0.f;
    mean[c] = m;
    rstd[c] = rsqrtf(v + 1e-5f);
}

__global__ void normalize_kernel(const float* __restrict__ x, float* __restrict__ xn,
                                 const float* __restrict__ mean, const float* __restrict__ rstd,
                                 const float* __restrict__ g, const float* __restrict__ b,
                                 int total, int din) {
    int i = blockIdx.x * blockDim.x + threadIdx.x;
    if (i >= total) return;
    int c = i % din;
    xn[i] = (x[i] - mean[c]) * rstd[c] * g[c] + b[c];
}

// ---------------- weight packing ----------------
// Column layout: [0,4F): W_j ; [4F,5F): skW ; [5F,5F+4H): vs ; [5F+4H,5F+8H): vd ; rest: 0
__global__ void pack_kernel(const float* __restrict__ W, const float* __restrict__ skW,
                            const float* __restrict__ As, const float* __restrict__ Ad,
                            float* __restrict__ Wp, int din, int H, int DOUT, int F, int LD) {
    int idx = blockIdx.x * blockDim.x + threadIdx.x;
    if (idx >= din * LD) return;
    int i = idx / LD;
    int col = idx % LD;
    float v = 0.f;
    if (col < 4 * F) {
        int j = col / F, f = col % F;
        v = W[((size_t)j * din + i) * F + f];
    } else if (col < 5 * F) {
        v = skW[(size_t)i * F + (col - 4 * F)];
    } else if (col < 5 * F + 8 * H) {
        int rem = col - 5 * F;
        const float* Amat = (rem < 4 * H) ? As : Ad;
        rem = rem % (4 * H);
        int j = rem / H, h = rem % H;
        float s = 0.f;
        for (int d = 0; d < DOUT; d++)
            s += W[((size_t)j * din + i) * F + h * DOUT + d] * Amat[((size_t)j * H + h) * DOUT + d];
        v = s;
    }
    Wp[(size_t)i * LD + col] = v;
}

// ---------------- fp32 tiled GEMM: C[M,Nc] = A[M,K] @ B[K,Nc] ----------------
__global__ __launch_bounds__(256)
void gemm_kernel(const float* __restrict__ A, const float* __restrict__ B,
                 float* __restrict__ C, int M, int Nc, int K) {
    const int BM = 128, BN = 64, BK = 16;
    __shared__ float As[BK][BM + 4];
    __shared__ float Bs[BK][BN + 4];
    int t = threadIdx.x;
    int row0 = blockIdx.x * BM;
    int col0 = blockIdx.y * BN;
    int tm = t >> 4, tn = t & 15;

    float acc[8][4];
#pragma unroll
    for (int i = 0; i < 8; i++)
#pragma unroll
        for (int j = 0; j < 4; j++) acc[i][j] = 0.f;

    int ar = t >> 2;            // 0..63
    int akc = (t & 3) << 2;     // 0,4,8,12
    int br = t >> 4;            // 0..15
    int bc = (t & 15) << 2;     // 0..60

    for (int k0 = 0; k0 < K; k0 += BK) {
#pragma unroll
        for (int half = 0; half < 2; half++) {
            int r = ar + half * 64;
            float4 av = make_float4(0.f, 0.f, 0.f, 0.f);
            if (row0 + r < M)
                av = *(const float4*)&A[(size_t)(row0 + r) * K + k0 + akc];
            As[akc + 0][r] = av.x;
            As[akc + 1][r] = av.y;
            As[akc + 2][r] = av.z;
            As[akc + 3][r] = av.w;
        }
        float4 bv = make_float4(0.f, 0.f, 0.f, 0.f);
        if (col0 + bc < Nc)
            bv = *(const float4*)&B[(size_t)(k0 + br) * Nc + col0 + bc];
        *(float4*)&Bs[br][bc] = bv;
        __syncthreads();
#pragma unroll
        for (int kk = 0; kk < BK; kk++) {
            float4 a0 = *(const float4*)&As[kk][tm * 8];
            float4 a1 = *(const float4*)&As[kk][tm * 8 + 4];
            float4 b4 = *(const float4*)&Bs[kk][tn * 4];
            float a[8] = {a0.x, a0.y, a0.z, a0.w, a1.x, a1.y, a1.z, a1.w};
            float bb[4] = {b4.x, b4.y, b4.z, b4.w};
#pragma unroll
            for (int i = 0; i < 8; i++)
#pragma unroll
                for (int j = 0; j < 4; j++) acc[i][j] += a[i] * bb[j];
        }
        __syncthreads();
    }
#pragma unroll
    for (int i = 0; i < 8; i++) {
        int r = row0 + tm * 8 + i;
        if (r >= M) continue;
#pragma unroll
        for (int j = 0; j < 4; j++) {
            int cc = col0 + tn * 4 + j;
            if (cc < Nc) C[(size_t)r * Nc + cc] = acc[i][j];
        }
    }
}

// ---------------- GAT message pass: per-dst online softmax per (class, head) ----------------
template <int F, int H, int DOUT, int LD>
__global__ void gat_message_kernel(const float* __restrict__ HB, const int* __restrict__ off,
                                   const int* __restrict__ ssrc, const unsigned char* __restrict__ scls,
                                   const float* __restrict__ skb, const float* __restrict__ cb,
                                   float* __restrict__ xout, int n) {
    constexpr int NPB = 256 / F;
    int node = blockIdx.x * NPB + threadIdx.x / F;
    if (node >= n) return;
    int f = threadIdx.x % F;
    int h = f / DOUT;
    const float* hrow = HB + (size_t)node * LD;

    float edv0 = hrow[5 * F + 4 * H + 0 * H + h];
    float edv1 = hrow[5 * F + 4 * H + 1 * H + h];
    float edv2 = hrow[5 * F + 4 * H + 2 * H + h];
    float edv3 = hrow[5 * F + 4 * H + 3 * H + h];

    float m0 = -3e38f, m1 = -3e38f, m2 = -3e38f, m3 = -3e38f;
    float s0 = 0.f, s1 = 0.f, s2 = 0.f, s3 = 0.f;
    float a0 = 0.f, a1 = 0.f, a2 = 0.f, a3 = 0.f;

    int i0 = off[node], i1 = off[node + 1];
    for (int i = i0; i < i1; i++) {
        int sN = ssrc[i];
        int c = scls[i];
        const float* srow = HB + (size_t)sN * LD;
#define GAT_UPD(cc, edv)                                        \
        {                                                       \
            float logit = srow[5 * F + cc * H + h] + edv;       \
            logit = logit > 0.f ? logit : 0.2f * logit;         \
            float hv = srow[cc * F + f];                        \
            float nm = fmaxf(m##cc, logit);                     \
            float sc = __expf(m##cc - nm);                      \
            float p  = __expf(logit - nm);                      \
            s##cc = s##cc * sc + p;                             \
            a##cc = a##cc * sc + p * hv;                        \
            m##cc = nm;                                         \
        }
        if (c == 0)      GAT_UPD(0, edv0)
        else if (c == 1) GAT_UPD(1, edv1)
        else if (c == 2) GAT_UPD(2, edv2)
        else if (c == 3) GAT_UPD(3, edv3)
#undef GAT_UPD
    }

    float out = hrow[4 * F + f] + skb[f]
              + cb[0 * F + f] + cb[1 * F + f] + cb[2 * F + f] + cb[3 * F + f];
    if (s0 > 0.f) out += a0 / s0;
    if (s1 > 0.f) out += a1 / s1;
    if (s2 > 0.f) out += a2 / s2;
    if (s3 > 0.f) out += a3 / s3;
    xout[(size_t)node * F + f] = fmaxf(out, 0.f);
}

// ---------------- launch ----------------
extern "C" void kernel_launch(void* const* d_in, const int* in_sizes, int n_in,
                              void* d_out, int out_size) {
    float *XA, *XB, *HB, *Wp, *sum, *sumsq, *mean, *rstd;
    int *deg, *off, *cnt, *ssrc;
    unsigned char* scls;
    cudaGetSymbolAddress((void**)&XA, g_XA);
    cudaGetSymbolAddress((void**)&XB, g_XB);
    cudaGetSymbolAddress((void**)&HB, g_HB);
    cudaGetSymbolAddress((void**)&Wp, g_Wp);
    cudaGetSymbolAddress((void**)&sum, g_sum);
    cudaGetSymbolAddress((void**)&sumsq, g_sumsq);
    cudaGetSymbolAddress((void**)&mean, g_mean);
    cudaGetSymbolAddress((void**)&rstd, g_rstd);
    cudaGetSymbolAddress((void**)&deg, g_deg);
    cudaGetSymbolAddress((void**)&off, g_off);
    cudaGetSymbolAddress((void**)&cnt, g_cnt);
    cudaGetSymbolAddress((void**)&ssrc, g_ssrc);
    cudaGetSymbolAddress((void**)&scls, g_scls);

    const float* x    = (const float*)d_in[0];
    const int* eidx   = (const int*)d_in[1];
    const int* eattr  = (const int*)d_in[2];
    int n = in_sizes[0] / 64;      // 50000
    int E = in_sizes[1] / 2;       // 800000

    // CSR by dst
    cudaMemsetAsync(deg, 0, n * sizeof(int));
    hist_kernel<<<(E + 255) / 256, 256>>>(eidx, deg, E, n);
    scan_kernel<<<1, 1024>>>(deg, off, n);
    cudaMemsetAsync(cnt, 0, n * sizeof(int));
    fill_kernel<<<(E + 255) / 256, 256>>>(eidx, eattr, off, cnt, ssrc, scls, E, n);

    const float* xin = x;
    for (int l = 0; l < 3; l++) {
        const float* W   = (const float*)d_in[3 + 8 * l + 0];
        const float* As  = (const float*)d_in[3 + 8 * l + 1];
        const float* Ad  = (const float*)d_in[3 + 8 * l + 2];
        const float* cb  = (const float*)d_in[3 + 8 * l + 3];
        const float* skW = (const float*)d_in[3 + 8 * l + 4];
        const float* skb = (const float*)d_in[3 + 8 * l + 5];
        const float* bng = (const float*)d_in[3 + 8 * l + 6];
        const float* bnb = (const float*)d_in[3 + 8 * l + 7];

        int din = (l == 0) ? 64 : 256;
        int H = (l == 2) ? 1 : 4;
        int DOUT = (l == 2) ? 2 : 64;
        int F = H * DOUT;
        int LD = (l == 2) ? LD2 : LDBIG;

        cudaMemsetAsync(sum, 0, 256 * sizeof(float));
        cudaMemsetAsync(sumsq, 0, 256 * sizeof(float));
        colstats_kernel<<<256, 256>>>(xin, sum, sumsq, n, din);
        finalize_kernel<<<1, 256>>>(sum, sumsq, mean, rstd, n, din);
        normalize_kernel<<<(n * din + 255) / 256, 256>>>(xin, XA, mean, rstd, bng, bnb, n * din, din);

        pack_kernel<<<(din * LD + 255) / 256, 256>>>(W, skW, As, Ad, Wp, din, H, DOUT, F, LD);

        dim3 ggrid((n + 127) / 128, (LD + 63) / 64);
        gemm_kernel<<<ggrid, 256>>>(XA, Wp, HB, n, LD, din);

        if (l < 2) {
            gat_message_kernel<256, 4, 64, LDBIG><<<n, 256>>>(HB, off, ssrc, scls, skb, cb, XB, n);
            xin = XB;
        } else {
            gat_message_kernel<2, 1, 2, LD2><<<(n + 127) / 128, 256>>>(HB, off, ssrc, scls, skb, cb, (float*)d_out, n);
        }
    }
}

// round 2
// speedup vs baseline: 1.3308x; 1.3308x over previous
#include <cuda_runtime.h>
#include <cuda_bf16.h>
#include <cstdint>

// Problem constants
#define NN 50000
#define EE 800000
#define LDBIG 1312   // 4*256 (W) + 256 (skip) + 16 (ES) + 16 (ED)
#define LD2   24     // 8 (W) + 2 (skip) + 4 (ES) + 4 (ED) + 6 pad

// ---------------- static device scratch (no allocation allowed) ----------------
__device__ float g_XA[(size_t)NN * 256];           // normalized x (tf32-rounded)
__device__ float g_XB[(size_t)NN * 256];           // layer output x
__device__ float g_HB[(size_t)NN * LDBIG];         // hidden buffer (h0..h3 | skip | ES | ED)
__device__ float g_Wp[256 * LDBIG];                // packed weights (tf32-rounded)
__device__ float g_sum[256], g_sumsq[256], g_mean[256], g_rstd[256];
__device__ int   g_deg[NN], g_off[NN + 1], g_cnt[NN];
__device__ int   g_ssrc[EE];
__device__ unsigned char g_scls[EE];

__device__ __forceinline__ float tf32r(float x) {
    asm("cvt.rna.tf32.f32 %0, %0;" : "+f"(x));
    return x;
}

// ---------------- CSR build ----------------
__global__ void hist_kernel(const int* __restrict__ eidx, int* __restrict__ deg, int E, int n) {
    int e = blockIdx.x * blockDim.x + threadIdx.x;
    if (e >= E) return;
    int d = eidx[E + e];
    if ((unsigned)d < (unsigned)n) atomicAdd(&deg[d], 1);
}

__global__ void scan_kernel(const int* __restrict__ deg, int* __restrict__ off, int n) {
    __shared__ int sm[1024];
    __shared__ int carry_s;
    int t = threadIdx.x;
    if (t == 0) { off[0] = 0; carry_s = 0; }
    __syncthreads();
    for (int base = 0; base < n; base += 1024) {
        int v = (base + t < n) ? deg[base + t] : 0;
        sm[t] = v;
        __syncthreads();
        for (int d = 1; d < 1024; d <<= 1) {
            int add = (t >= d) ? sm[t - d] : 0;
            __syncthreads();
            sm[t] += add;
            __syncthreads();
        }
        if (base + t < n) off[base + t + 1] = sm[t] + carry_s;
        __syncthreads();
        if (t == 1023) carry_s += sm[1023];
        __syncthreads();
    }
}

__global__ void fill_kernel(const int* __restrict__ eidx, const int* __restrict__ eattr,
                            const int* __restrict__ off, int* __restrict__ cnt,
                            int* __restrict__ ssrc, unsigned char* __restrict__ scls,
                            int E, int n) {
    int e = blockIdx.x * blockDim.x + threadIdx.x;
    if (e >= E) return;
    int s = eidx[e];
    int d = eidx[E + e];
    int c = eattr[e];
    if ((unsigned)d >= (unsigned)n) return;
    int pos = off[d] + atomicAdd(&cnt[d], 1);
    ssrc[pos] = s;
    scls[pos] = (unsigned char)((c >= 0 && c < 4) ? c : 255);
}

// ---------------- batchnorm ----------------
__global__ void colstats_kernel(const float* __restrict__ x, float* __restrict__ sum,
                                float* __restrict__ sumsq, int n, int din) {
    int t = threadIdx.x;
    int c = t % din;
    int rpb = blockDim.x / din;
    int r0 = blockIdx.x * rpb + t / din;
    int rstride = gridDim.x * rpb;
    float s = 0.f, q = 0.f;
    for (int r = r0; r < n; r += rstride) {
        float v = x[(size_t)r * din + c];
        s += v; q += v * v;
    }
    atomicAdd(&sum[c], s);
    atomicAdd(&sumsq[c], q);
}

__global__ void finalize_kernel(const float* __restrict__ sum, const float* __restrict__ sumsq,
                                float* __restrict__ mean, float* __restrict__ rstd, int n, int din) {
    int c = threadIdx.x;
    if (c >= din) return;
    float m = sum[c] / (float)n;
    float v = sumsq[c] / (float)n - m * m;
    v = v > 0.f ? v : 0.f;
    mean[c] = m;
    rstd[c] = rsqrtf(v + 1e-5f);
}

__global__ void normalize_kernel(const float* __restrict__ x, float* __restrict__ xn,
                                 const float* __restrict__ mean, const float* __restrict__ rstd,
                                 const float* __restrict__ g, const float* __restrict__ b,
                                 int total, int din) {
    int i = blockIdx.x * blockDim.x + threadIdx.x;
    if (i >= total) return;
    int c = i % din;
    xn[i] = tf32r((x[i] - mean[c]) * rstd[c] * g[c] + b[c]);
}

// ---------------- weight packing ----------------
// Column layout: [0,4F): W_j ; [4F,5F): skW ; [5F,5F+4H): vs ; [5F+4H,5F+8H): vd ; rest: 0
__global__ void pack_kernel(const float* __restrict__ W, const float* __restrict__ skW,
                            const float* __restrict__ As, const float* __restrict__ Ad,
                            float* __restrict__ Wp, int din, int H, int DOUT, int F, int LD) {
    int idx = blockIdx.x * blockDim.x + threadIdx.x;
    if (idx >= din * LD) return;
    int i = idx / LD;
    int col = idx % LD;
    float v = 0.f;
    if (col < 4 * F) {
        int j = col / F, f = col % F;
        v = W[((size_t)j * din + i) * F + f];
    } else if (col < 5 * F) {
        v = skW[(size_t)i * F + (col - 4 * F)];
    } else if (col < 5 * F + 8 * H) {
        int rem = col - 5 * F;
        const float* Amat = (rem < 4 * H) ? As : Ad;
        rem = rem % (4 * H);
        int j = rem / H, h = rem % H;
        float s = 0.f;
        for (int d = 0; d < DOUT; d++)
            s += W[((size_t)j * din + i) * F + h * DOUT + d] * Amat[((size_t)j * H + h) * DOUT + d];
        v = s;
    }
    Wp[(size_t)i * LD + col] = tf32r(v);
}

// ---------------- TF32 tensor-core GEMM: C[M,Nc] = A[M,K] @ B[K,Nc] ----------------
__device__ __forceinline__ void mma_tf32(float c[4],
                                         uint32_t a0, uint32_t a1, uint32_t a2, uint32_t a3,
                                         uint32_t b0, uint32_t b1) {
    asm volatile(
        "mma.sync.aligned.m16n8k8.row.col.f32.tf32.tf32.f32 "
        "{%0,%1,%2,%3}, {%4,%5,%6,%7}, {%8,%9}, {%0,%1,%2,%3};"
        : "+f"(c[0]), "+f"(c[1]), "+f"(c[2]), "+f"(c[3])
        : "r"(a0), "r"(a1), "r"(a2), "r"(a3), "r"(b0), "r"(b1));
}

#define GBM 128
#define GBN 64
#define GBK 32

__global__ __launch_bounds__(256)
void gemm_tc_kernel(const float* __restrict__ A, const float* __restrict__ B,
                    float* __restrict__ C, int M, int Nc, int K) {
    __shared__ float As[GBM][GBK + 4];   // 128 x 36 : frag bank = (4*lr + lc) % 32, conflict-free
    __shared__ float Bs[GBK][GBN + 8];   // 32 x 72  : frag bank = (8*lc + lr) % 32, conflict-free
    int tid = threadIdx.x;
    int wid = tid >> 5, lane = tid & 31;
    int wm = wid & 3, wn = wid >> 2;     // warps 4 (m) x 2 (n)
    int lr = lane >> 2, lc = lane & 3;
    int row0 = blockIdx.x * GBM, col0 = blockIdx.y * GBN;

    float acc[2][4][4];
#pragma unroll
    for (int mt = 0; mt < 2; mt++)
#pragma unroll
        for (int nt = 0; nt < 4; nt++)
#pragma unroll
            for (int i = 0; i < 4; i++) acc[mt][nt][i] = 0.f;

    int arow = tid >> 3, akc = (tid & 7) << 2;  // A: 32 rows/pass, 4 passes
    int bk = tid >> 4, bn4 = (tid & 15) << 2;   // B: 16 k/pass, 2 passes

    for (int k0 = 0; k0 < K; k0 += GBK) {
#pragma unroll
        for (int p = 0; p < 4; p++) {
            int r = arow + p * 32;
            float4 v = make_float4(0.f, 0.f, 0.f, 0.f);
            if (row0 + r < M)
                v = *(const float4*)&A[(size_t)(row0 + r) * K + k0 + akc];
            *(float4*)&As[r][akc] = v;
        }
#pragma unroll
        for (int p = 0; p < 2; p++) {
            int kk = bk + p * 16;
            float4 v = make_float4(0.f, 0.f, 0.f, 0.f);
            if (col0 + bn4 < Nc)
                v = *(const float4*)&B[(size_t)(k0 + kk) * Nc + col0 + bn4];
            *(float4*)&Bs[kk][bn4] = v;
        }
        __syncthreads();
#pragma unroll
        for (int ks = 0; ks < GBK; ks += 8) {
            uint32_t af[2][4], bf[4][2];
#pragma unroll
            for (int mt = 0; mt < 2; mt++) {
                int mrow = wm * 32 + mt * 16 + lr;
                af[mt][0] = __float_as_uint(As[mrow][ks + lc]);
                af[mt][1] = __float_as_uint(As[mrow + 8][ks + lc]);
                af[mt][2] = __float_as_uint(As[mrow][ks + lc + 4]);
                af[mt][3] = __float_as_uint(As[mrow + 8][ks + lc + 4]);
            }
#pragma unroll
            for (int nt = 0; nt < 4; nt++) {
                int ncol = wn * 32 + nt * 8 + lr;
                bf[nt][0] = __float_as_uint(Bs[ks + lc][ncol]);
                bf[nt][1] = __float_as_uint(Bs[ks + lc + 4][ncol]);
            }
#pragma unroll
            for (int mt = 0; mt < 2; mt++)
#pragma unroll
                for (int nt = 0; nt < 4; nt++)
                    mma_tf32(acc[mt][nt], af[mt][0], af[mt][1], af[mt][2], af[mt][3],
                             bf[nt][0], bf[nt][1]);
        }
        __syncthreads();
    }

#pragma unroll
    for (int mt = 0; mt < 2; mt++) {
        int rbase = row0 + wm * 32 + mt * 16 + lr;
#pragma unroll
        for (int nt = 0; nt < 4; nt++) {
            int cbase = col0 + wn * 32 + nt * 8 + lc * 2;
            if (cbase + 1 < Nc || cbase + 1 == Nc - 0) {}
            if (rbase < M && cbase + 1 < Nc + 0 && cbase < Nc) {
                C[(size_t)rbase * Nc + cbase]     = acc[mt][nt][0];
                C[(size_t)rbase * Nc + cbase + 1] = acc[mt][nt][1];
            }
            if (rbase + 8 < M && cbase + 1 < Nc + 0 && cbase < Nc) {
                C[(size_t)(rbase + 8) * Nc + cbase]     = acc[mt][nt][2];
                C[(size_t)(rbase + 8) * Nc + cbase + 1] = acc[mt][nt][3];
            }
        }
    }
}

// ---------------- GAT message pass: per-dst online softmax per (class, head) ----------------
template <int F, int H, int DOUT, int LD>
__global__ void gat_message_kernel(const float* __restrict__ HB, const int* __restrict__ off,
                                   const int* __restrict__ ssrc, const unsigned char* __restrict__ scls,
                                   const float* __restrict__ skb, const float* __restrict__ cb,
                                   float* __restrict__ xout, int n) {
    constexpr int NPB = 256 / F;
    int node = blockIdx.x * NPB + threadIdx.x / F;
    if (node >= n) return;
    int f = threadIdx.x % F;
    int h = f / DOUT;
    const float* hrow = HB + (size_t)node * LD;

    float edv0 = hrow[5 * F + 4 * H + 0 * H + h];
    float edv1 = hrow[5 * F + 4 * H + 1 * H + h];
    float edv2 = hrow[5 * F + 4 * H + 2 * H + h];
    float edv3 = hrow[5 * F + 4 * H + 3 * H + h];

    float m0 = -3e38f, m1 = -3e38f, m2 = -3e38f, m3 = -3e38f;
    float s0 = 0.f, s1 = 0.f, s2 = 0.f, s3 = 0.f;
    float a0 = 0.f, a1 = 0.f, a2 = 0.f, a3 = 0.f;

    int i0 = off[node], i1 = off[node + 1];
    for (int i = i0; i < i1; i++) {
        int sN = ssrc[i];
        int c = scls[i];
        const float* srow = HB + (size_t)sN * LD;
#define GAT_UPD(cc, edv)                                        \
        {                                                       \
            float logit = srow[5 * F + cc * H + h] + edv;       \
            logit = logit > 0.f ? logit : 0.2f * logit;         \
            float hv = srow[cc * F + f];                        \
            float nm = fmaxf(m##cc, logit);                     \
            float sc = __expf(m##cc - nm);                      \
            float p  = __expf(logit - nm);                      \
            s##cc = s##cc * sc + p;                             \
            a##cc = a##cc * sc + p * hv;                        \
            m##cc = nm;                                         \
        }
        if (c == 0)      GAT_UPD(0, edv0)
        else if (c == 1) GAT_UPD(1, edv1)
        else if (c == 2) GAT_UPD(2, edv2)
        else if (c == 3) GAT_UPD(3, edv3)
#undef GAT_UPD
    }

    float out = hrow[4 * F + f] + skb[f]
              + cb[0 * F + f] + cb[1 * F + f] + cb[2 * F + f] + cb[3 * F + f];
    if (s0 > 0.f) out += a0 / s0;
    if (s1 > 0.f) out += a1 / s1;
    if (s2 > 0.f) out += a2 / s2;
    if (s3 > 0.f) out += a3 / s3;
    xout[(size_t)node * F + f] = fmaxf(out, 0.f);
}

// ---------------- launch ----------------
extern "C" void kernel_launch(void* const* d_in, const int* in_sizes, int n_in,
                              void* d_out, int out_size) {
    float *XA, *XB, *HB, *Wp, *sum, *sumsq, *mean, *rstd;
    int *deg, *off, *cnt, *ssrc;
    unsigned char* scls;
    cudaGetSymbolAddress((void**)&XA, g_XA);
    cudaGetSymbolAddress((void**)&XB, g_XB);
    cudaGetSymbolAddress((void**)&HB, g_HB);
    cudaGetSymbolAddress((void**)&Wp, g_Wp);
    cudaGetSymbolAddress((void**)&sum, g_sum);
    cudaGetSymbolAddress((void**)&sumsq, g_sumsq);
    cudaGetSymbolAddress((void**)&mean, g_mean);
    cudaGetSymbolAddress((void**)&rstd, g_rstd);
    cudaGetSymbolAddress((void**)&deg, g_deg);
    cudaGetSymbolAddress((void**)&off, g_off);
    cudaGetSymbolAddress((void**)&cnt, g_cnt);
    cudaGetSymbolAddress((void**)&ssrc, g_ssrc);
    cudaGetSymbolAddress((void**)&scls, g_scls);

    const float* x    = (const float*)d_in[0];
    const int* eidx   = (const int*)d_in[1];
    const int* eattr  = (const int*)d_in[2];
    int n = in_sizes[0] / 64;      // 50000
    int E = in_sizes[1] / 2;       // 800000

    // CSR by dst
    cudaMemsetAsync(deg, 0, n * sizeof(int));
    hist_kernel<<<(E + 255) / 256, 256>>>(eidx, deg, E, n);
    scan_kernel<<<1, 1024>>>(deg, off, n);
    cudaMemsetAsync(cnt, 0, n * sizeof(int));
    fill_kernel<<<(E + 255) / 256, 256>>>(eidx, eattr, off, cnt, ssrc, scls, E, n);

    const float* xin = x;
    for (int l = 0; l < 3; l++) {
        const float* W   = (const float*)d_in[3 + 8 * l + 0];
        const float* As  = (const float*)d_in[3 + 8 * l + 1];
        const float* Ad  = (const float*)d_in[3 + 8 * l + 2];
        const float* cb  = (const float*)d_in[3 + 8 * l + 3];
        const float* skW = (const float*)d_in[3 + 8 * l + 4];
        const float* skb = (const float*)d_in[3 + 8 * l + 5];
        const float* bng = (const float*)d_in[3 + 8 * l + 6];
        const float* bnb = (const float*)d_in[3 + 8 * l + 7];

        int din = (l == 0) ? 64 : 256;
        int H = (l == 2) ? 1 : 4;
        int DOUT = (l == 2) ? 2 : 64;
        int F = H * DOUT;
        int LD = (l == 2) ? LD2 : LDBIG;

        cudaMemsetAsync(sum, 0, 256 * sizeof(float));
        cudaMemsetAsync(sumsq, 0, 256 * sizeof(float));
        colstats_kernel<<<256, 256>>>(xin, sum, sumsq, n, din);
        finalize_kernel<<<1, 256>>>(sum, sumsq, mean, rstd, n, din);
        normalize_kernel<<<(n * din + 255) / 256, 256>>>(xin, XA, mean, rstd, bng, bnb, n * din, din);

        pack_kernel<<<(din * LD + 255) / 256, 256>>>(W, skW, As, Ad, Wp, din, H, DOUT, F, LD);

        dim3 ggrid((n + GBM - 1) / GBM, (LD + GBN - 1) / GBN);
        gemm_tc_kernel<<<ggrid, 256>>>(XA, Wp, HB, n, LD, din);

        if (l < 2) {
            gat_message_kernel<256, 4, 64, LDBIG><<<n, 256>>>(HB, off, ssrc, scls, skb, cb, XB, n);
            xin = XB;
        } else {
            gat_message_kernel<2, 1, 2, LD2><<<(n + 127) / 128, 256>>>(HB, off, ssrc, scls, skb, cb, (float*)d_out, n);
        }
    }
}